// round 1
// baseline (speedup 1.0000x reference)
#include <cuda_runtime.h>
#include <cstdint>

// Masked LeNet-C3 conv: out[n,oc,y,x] = b[oc] + sum_{ic,ky,kx} x[n,ic,y+ky,x+kx] * W[oc,ic,ky,kx] * MAP[ic,oc]
// x: [64,6,512,512] f32, W: [16,6,5,5] f32, b: [16] f32, out: [N,16,508,508] f32 (VALID)

#define NIC 6
#define NOC 16
#define IH 512
#define IW 512
#define OH 508
#define OW 508
#define TILE_W 64
#define TILE_H 8
#define IN_H   12           // TILE_H + 4
#define IN_WS  72           // interleaved storage: cols 0..35 at even slots, cols 32..67 at odd slots (32..35 duplicated)
#define NTHREADS 256

// MAP[ic][oc] connectivity (LeNet-5 C3 table)
__device__ const float C3_MASK[NIC][NOC] = {
    {1,0,0,0,1,1,1,0,0,1,1,1,1,0,1,1},
    {1,1,0,0,0,1,1,1,0,0,1,1,1,1,0,1},
    {1,1,1,0,0,0,1,1,1,0,0,1,0,1,1,1},
    {0,1,1,1,0,0,1,1,1,1,0,0,1,0,1,1},
    {0,0,1,1,1,0,0,1,1,1,1,0,1,1,0,1},
    {0,0,0,1,1,1,0,0,1,1,1,1,0,1,1,1},
};

// Packed f32x2 FMA: acc(2xf32) += a(2xf32) * w(2xf32). FFMA2 in SASS (PTX-only form).
__device__ __forceinline__ void fma2(unsigned long long& acc,
                                     unsigned long long a,
                                     unsigned long long w) {
    asm("fma.rn.f32x2 %0, %1, %2, %0;" : "+l"(acc) : "l"(a), "l"(w));
}

__global__ __launch_bounds__(NTHREADS)
void conv_c3_kernel(const float* __restrict__ x,
                    const float* __restrict__ W,
                    const float* __restrict__ b,
                    float* __restrict__ out)
{
    // smem: input tile (interleaved pairs), duplicated weight pairs, bias
    __shared__ __align__(16) float s_in[NIC][IN_H][IN_WS];          // 6*12*72*4  = 20736 B
    __shared__ __align__(16) float s_w[150 * 2 * NOC];              // 150*32*4   = 19200 B, layout: [g=ic*25+k][oc][dup2]
    __shared__ float s_b[NOC];

    const int tid = threadIdx.x;
    const int n   = blockIdx.z;
    const int by0 = blockIdx.y * TILE_H;   // output-row origin
    const int bx0 = blockIdx.x * TILE_W;   // output-col origin

    // ---- Load input tile into interleaved smem ----
    // slot s (even)  -> col = s/2        (0..35)   [pair base]
    // slot s (odd)   -> col = s/2 + 32   (32..67)  [pair partner; 32..35 duplicated]
    const float* xin = x + (size_t)n * NIC * IH * IW;
    #pragma unroll 1
    for (int idx = tid; idx < NIC * IN_H * IN_WS; idx += NTHREADS) {
        int ic = idx / (IN_H * IN_WS);
        int r  = (idx / IN_WS) % IN_H;
        int s  = idx % IN_WS;
        int col = (s & 1) ? ((s >> 1) + 32) : (s >> 1);
        int gy = by0 + r;
        int gx = bx0 + col;
        float v = 0.0f;
        if (gy < IH && gx < IW)
            v = __ldg(&xin[(ic * IH + gy) * IW + gx]);
        s_in[ic][r][s] = v;
    }

    // ---- Load masked weights, duplicated as (w,w) pairs ----
    #pragma unroll 1
    for (int idx = tid; idx < NOC * 150; idx += NTHREADS) {
        int oc  = idx / 150;
        int rem = idx % 150;        // ic*25 + k
        int ic  = rem / 25;
        float wv = W[oc * 150 + rem] * C3_MASK[ic][oc];
        s_w[rem * 32 + oc * 2]     = wv;
        s_w[rem * 32 + oc * 2 + 1] = wv;
    }
    if (tid < NOC) s_b[tid] = b[tid];
    __syncthreads();

    // ---- Compute: each thread owns output pixels (y, x0) and (y, x0+32) for all 16 oc ----
    const int tx = tid & 31;
    const int ty = tid >> 5;

    unsigned long long acc[NOC];
    #pragma unroll
    for (int i = 0; i < NOC; i++) acc[i] = 0ull;

    #pragma unroll 1
    for (int ic = 0; ic < NIC; ic++) {
        #pragma unroll
        for (int k = 0; k < 25; k++) {
            const int ky = k / 5;
            const int kx = k % 5;
            // one aligned LDS.64: pixel pair (tx+kx, tx+32+kx)
            unsigned long long xv = *reinterpret_cast<const unsigned long long*>(
                &s_in[ic][ty + ky][2 * (tx + kx)]);
            const ulonglong2* wp = reinterpret_cast<const ulonglong2*>(
                &s_w[(ic * 25 + k) * 32]);
            #pragma unroll
            for (int j = 0; j < 8; j++) {
                ulonglong2 w2 = wp[j];          // LDS.128 (uniform broadcast): oc 2j, 2j+1
                fma2(acc[2 * j],     xv, w2.x);
                fma2(acc[2 * j + 1], xv, w2.y);
            }
        }
    }

    // ---- Epilogue: add bias, store ----
    const int y  = by0 + ty;
    const int x0 = bx0 + tx;
    const int x1 = x0 + 32;
    if (y < OH) {
        #pragma unroll
        for (int oc = 0; oc < NOC; oc++) {
            float bo = s_b[oc];
            float lo = __uint_as_float((unsigned)(acc[oc] & 0xffffffffull));
            float hi = __uint_as_float((unsigned)(acc[oc] >> 32));
            size_t base = ((size_t)(n * NOC + oc) * OH + y) * OW;
            if (x0 < OW) out[base + x0] = lo + bo;
            if (x1 < OW) out[base + x1] = hi + bo;
        }
    }
}

extern "C" void kernel_launch(void* const* d_in, const int* in_sizes, int n_in,
                              void* d_out, int out_size) {
    const float* x = (const float*)d_in[0];
    const float* W = (const float*)d_in[1];
    const float* b = (const float*)d_in[2];
    float* out = (float*)d_out;

    const int n_batch = in_sizes[0] / (NIC * IH * IW);   // 64
    dim3 grid((OW + TILE_W - 1) / TILE_W,   // 8
              (OH + TILE_H - 1) / TILE_H,   // 64
              n_batch);                      // 64
    conv_c3_kernel<<<grid, NTHREADS>>>(x, W, b, out);
}

// round 3
// speedup vs baseline: 1.2348x; 1.2348x over previous
#include <cuda_runtime.h>
#include <cstdint>

// Masked LeNet-C3 conv on GB300.
// x: [64,6,512,512] f32, W: [16,6,5,5] f32, b: [16] f32 -> out: [64,16,508,508] f32 (VALID 5x5)
// Strategy: direct conv, 64x32 output tile per block, 4 rows x (pixel,pixel+32) pair x 16 oc per thread,
// f32x2 packed FMAs, compile-time skipping of masked (ic,oc) connections (10 active oc per ic).

#define NIC 6
#define NOC 16
#define IH 512
#define IW 512
#define OH 508
#define OW 508
#define TILE_W 64
#define TILE_H 32
#define RPT 4            // output rows per thread
#define IN_ROWS 36       // TILE_H + 4
#define IN_WS 72         // interleaved: slot 2c -> col c (c<36), slot 2c+1 -> col c+32 (c<36)
#define NTHREADS 256
#define NACT 10          // active output channels per input channel

typedef unsigned long long ull;

// Active oc list per ic (LeNet-5 C3 table; 10 entries each).
// constexpr FUNCTION (not namespace-scope array) so device code can use it
// without --expt-relaxed-constexpr; with compile-time args it folds to a constant.
__host__ __device__ constexpr int active(int ic, int slot) {
    constexpr int A[NIC][NACT] = {
        {0, 4, 5, 6, 9, 10, 11, 12, 14, 15},
        {0, 1, 5, 6, 7, 10, 11, 12, 13, 15},
        {0, 1, 2, 6, 7, 8, 11, 13, 14, 15},
        {1, 2, 3, 6, 7, 8, 9, 12, 14, 15},
        {2, 3, 4, 7, 8, 9, 10, 12, 13, 15},
        {3, 4, 5, 8, 9, 10, 11, 13, 14, 15},
    };
    return A[ic][slot];
}

__device__ __forceinline__ void fma2(ull& acc, ull a, ull w) {
    asm("fma.rn.f32x2 %0, %1, %2, %0;" : "+l"(acc) : "l"(a), "l"(w));
}

// Process one input channel; IC is compile-time so active(IC, slot) folds to
// constant register indices (acc stays in registers).
template<int IC>
__device__ __forceinline__ void conv_ic(const float* __restrict__ s_in,
                                        const float* __restrict__ s_w,
                                        ull acc[RPT][NOC],
                                        int row0, int tx)
{
    const float* in_ic = s_in + IC * IN_ROWS * IN_WS;
    #pragma unroll 1
    for (int ky = 0; ky < 5; ky++) {
        #pragma unroll
        for (int kx = 0; kx < 5; kx++) {
            const int k = ky * 5 + kx;
            const ulonglong2* wp = reinterpret_cast<const ulonglong2*>(
                s_w + (IC * 25 + k) * (2 * NACT));
            ulonglong2 w0 = wp[0];   // slots 0,1 (each = duplicated weight pair)
            ulonglong2 w1 = wp[1];   // slots 2,3
            ulonglong2 w2 = wp[2];   // slots 4,5
            ulonglong2 w3 = wp[3];   // slots 6,7
            ulonglong2 w4 = wp[4];   // slots 8,9
            #pragma unroll
            for (int r = 0; r < RPT; r++) {
                ull xv = *reinterpret_cast<const ull*>(
                    in_ic + (row0 + r + ky) * IN_WS + 2 * (tx + kx));
                fma2(acc[r][active(IC, 0)], xv, w0.x);
                fma2(acc[r][active(IC, 1)], xv, w0.y);
                fma2(acc[r][active(IC, 2)], xv, w1.x);
                fma2(acc[r][active(IC, 3)], xv, w1.y);
                fma2(acc[r][active(IC, 4)], xv, w2.x);
                fma2(acc[r][active(IC, 5)], xv, w2.y);
                fma2(acc[r][active(IC, 6)], xv, w3.x);
                fma2(acc[r][active(IC, 7)], xv, w3.y);
                fma2(acc[r][active(IC, 8)], xv, w4.x);
                fma2(acc[r][active(IC, 9)], xv, w4.y);
            }
        }
    }
}

__global__ __launch_bounds__(NTHREADS, 1)
void conv_c3_kernel(const float* __restrict__ x,
                    const float* __restrict__ W,
                    const float* __restrict__ b,
                    float* __restrict__ out)
{
    extern __shared__ float smem[];
    float* s_in = smem;                                   // 6*36*72 = 15552 floats
    float* s_w  = smem + NIC * IN_ROWS * IN_WS;           // 6*25*20 = 3000 floats
    float* s_b  = s_w + NIC * 25 * 2 * NACT;              // 16 floats

    const int tid  = threadIdx.x;
    const int lane = tid & 31;
    const int warp = tid >> 5;
    const int n    = blockIdx.z;
    const int by0  = blockIdx.y * TILE_H;
    const int bx0  = blockIdx.x * TILE_W;

    // ---- Load input tile (coalesced LDG, interleaved STS) ----
    const float* xin = x + (size_t)n * NIC * IH * IW;
    #pragma unroll 1
    for (int rowi = warp; rowi < NIC * IN_ROWS; rowi += NTHREADS / 32) {
        int ic = rowi / IN_ROWS;
        int r  = rowi % IN_ROWS;
        int gy = by0 + r;
        const float* src = xin + ((size_t)ic * IH + gy) * IW;
        float* dstrow = s_in + (ic * IN_ROWS + r) * IN_WS;
        #pragma unroll
        for (int cc = 0; cc < 3; cc++) {
            int c = lane + cc * 32;
            if (c < 68) {
                int gx = bx0 + c;
                float v = 0.0f;
                if (gy < IH && gx < IW) v = __ldg(src + gx);
                if (c < 36)  dstrow[2 * c] = v;
                if (c >= 32) dstrow[2 * (c - 32) + 1] = v;
            }
        }
    }

    // ---- Load packed active weights, duplicated as (w,w) pairs ----
    #pragma unroll 1
    for (int idx = tid; idx < NIC * 25 * NACT; idx += NTHREADS) {
        int ic   = idx / (25 * NACT);
        int rem  = idx % (25 * NACT);
        int k    = rem / NACT;
        int slot = rem % NACT;
        int oc   = active(ic, slot);
        float wv = W[oc * (NIC * 25) + ic * 25 + k];
        s_w[(ic * 25 + k) * (2 * NACT) + 2 * slot]     = wv;
        s_w[(ic * 25 + k) * (2 * NACT) + 2 * slot + 1] = wv;
    }
    if (tid < NOC) s_b[tid] = b[tid];
    __syncthreads();

    // ---- Compute ----
    const int tx   = lane;           // owns output cols bx0+tx and bx0+tx+32
    const int row0 = warp * RPT;     // owns output rows by0+row0 .. +3

    ull acc[RPT][NOC];
    #pragma unroll
    for (int r = 0; r < RPT; r++)
        #pragma unroll
        for (int o = 0; o < NOC; o++) acc[r][o] = 0ull;

    conv_ic<0>(s_in, s_w, acc, row0, tx);
    conv_ic<1>(s_in, s_w, acc, row0, tx);
    conv_ic<2>(s_in, s_w, acc, row0, tx);
    conv_ic<3>(s_in, s_w, acc, row0, tx);
    conv_ic<4>(s_in, s_w, acc, row0, tx);
    conv_ic<5>(s_in, s_w, acc, row0, tx);

    // ---- Epilogue: add bias, store ----
    const int x0 = bx0 + tx;
    const int x1 = x0 + 32;
    #pragma unroll
    for (int r = 0; r < RPT; r++) {
        int y = by0 + row0 + r;
        if (y >= OH) continue;
        #pragma unroll
        for (int oc = 0; oc < NOC; oc++) {
            float bo = s_b[oc];
            float lo = __uint_as_float((unsigned)(acc[r][oc] & 0xffffffffull)) + bo;
            float hi = __uint_as_float((unsigned)(acc[r][oc] >> 32)) + bo;
            size_t base = ((size_t)(n * NOC + oc) * OH + y) * OW;
            if (x0 < OW) out[base + x0] = lo;
            if (x1 < OW) out[base + x1] = hi;
        }
    }
}

extern "C" void kernel_launch(void* const* d_in, const int* in_sizes, int n_in,
                              void* d_out, int out_size) {
    const float* x = (const float*)d_in[0];
    const float* W = (const float*)d_in[1];
    const float* b = (const float*)d_in[2];
    float* out = (float*)d_out;

    const int smem_bytes = (NIC * IN_ROWS * IN_WS + NIC * 25 * 2 * NACT + NOC) * 4;
    cudaFuncSetAttribute(conv_c3_kernel,
                         cudaFuncAttributeMaxDynamicSharedMemorySize, smem_bytes);

    const int n_batch = in_sizes[0] / (NIC * IH * IW);   // 64
    dim3 grid((OW + TILE_W - 1) / TILE_W,    // 8
              (OH + TILE_H - 1) / TILE_H,    // 16
              n_batch);                       // 64
    conv_c3_kernel<<<grid, NTHREADS, smem_bytes>>>(x, W, b, out);
}

// round 4
// speedup vs baseline: 1.6953x; 1.3730x over previous
#include <cuda_runtime.h>
#include <cstdint>

// Masked LeNet-C3 conv on GB300.
// x: [64,6,512,512] f32, W: [16,6,5,5] f32, b: [16] f32 -> out: [64,16,508,508] f32 (VALID 5x5)
// Round 4: RPT=2, 2 blocks/SM (16 warps) to fix the occupancy/latency bound seen in round 3.

#define NIC 6
#define NOC 16
#define IH 512
#define IW 512
#define OH 508
#define OW 508
#define TILE_W 64
#define TILE_H 16
#define RPT 2            // output rows per thread (8 warps x 2 = 16 rows)
#define IN_ROWS 20       // TILE_H + 4
#define IN_WS 72         // interleaved: slot 2c -> col c (c<36), slot 2c+1 -> col c+32 (c<36)
#define NTHREADS 256
#define NACT 10          // active output channels per input channel

typedef unsigned long long ull;

// Active oc list per ic (LeNet-5 C3 table). constexpr FUNCTION so device code
// can fold it at compile time without --expt-relaxed-constexpr.
__host__ __device__ constexpr int active(int ic, int slot) {
    constexpr int A[NIC][NACT] = {
        {0, 4, 5, 6, 9, 10, 11, 12, 14, 15},
        {0, 1, 5, 6, 7, 10, 11, 12, 13, 15},
        {0, 1, 2, 6, 7, 8, 11, 13, 14, 15},
        {1, 2, 3, 6, 7, 8, 9, 12, 14, 15},
        {2, 3, 4, 7, 8, 9, 10, 12, 13, 15},
        {3, 4, 5, 8, 9, 10, 11, 13, 14, 15},
    };
    return A[ic][slot];
}

__device__ __forceinline__ void fma2(ull& acc, ull a, ull w) {
    asm("fma.rn.f32x2 %0, %1, %2, %0;" : "+l"(acc) : "l"(a), "l"(w));
}

template<int IC>
__device__ __forceinline__ void conv_ic(const float* __restrict__ s_in,
                                        const float* __restrict__ s_w,
                                        ull acc[RPT][NOC],
                                        int row0, int tx)
{
    const float* in_ic = s_in + IC * IN_ROWS * IN_WS;
    #pragma unroll 1
    for (int ky = 0; ky < 5; ky++) {
        #pragma unroll
        for (int kx = 0; kx < 5; kx++) {
            const int k = ky * 5 + kx;
            const ulonglong2* wp = reinterpret_cast<const ulonglong2*>(
                s_w + (IC * 25 + k) * (2 * NACT));
            ulonglong2 w0 = wp[0];   // slots 0,1 (each = duplicated weight pair)
            ulonglong2 w1 = wp[1];   // slots 2,3
            ulonglong2 w2 = wp[2];   // slots 4,5
            ulonglong2 w3 = wp[3];   // slots 6,7
            ulonglong2 w4 = wp[4];   // slots 8,9
            #pragma unroll
            for (int r = 0; r < RPT; r++) {
                ull xv = *reinterpret_cast<const ull*>(
                    in_ic + (row0 + r + ky) * IN_WS + 2 * (tx + kx));
                fma2(acc[r][active(IC, 0)], xv, w0.x);
                fma2(acc[r][active(IC, 1)], xv, w0.y);
                fma2(acc[r][active(IC, 2)], xv, w1.x);
                fma2(acc[r][active(IC, 3)], xv, w1.y);
                fma2(acc[r][active(IC, 4)], xv, w2.x);
                fma2(acc[r][active(IC, 5)], xv, w2.y);
                fma2(acc[r][active(IC, 6)], xv, w3.x);
                fma2(acc[r][active(IC, 7)], xv, w3.y);
                fma2(acc[r][active(IC, 8)], xv, w4.x);
                fma2(acc[r][active(IC, 9)], xv, w4.y);
            }
        }
    }
}

__global__ __launch_bounds__(NTHREADS, 2)
void conv_c3_kernel(const float* __restrict__ x,
                    const float* __restrict__ W,
                    const float* __restrict__ b,
                    float* __restrict__ out)
{
    extern __shared__ float smem[];
    float* s_in = smem;                                   // 6*20*72 = 8640 floats
    float* s_w  = smem + NIC * IN_ROWS * IN_WS;           // 6*25*20 = 3000 floats
    float* s_b  = s_w + NIC * 25 * 2 * NACT;              // 16 floats

    const int tid  = threadIdx.x;
    const int lane = tid & 31;
    const int warp = tid >> 5;
    const int n    = blockIdx.z;
    const int by0  = blockIdx.y * TILE_H;
    const int bx0  = blockIdx.x * TILE_W;

    // ---- Load input tile (coalesced LDG, interleaved STS) ----
    const float* xin = x + (size_t)n * NIC * IH * IW;
    #pragma unroll 1
    for (int rowi = warp; rowi < NIC * IN_ROWS; rowi += NTHREADS / 32) {
        int ic = rowi / IN_ROWS;
        int r  = rowi % IN_ROWS;
        int gy = by0 + r;
        const float* src = xin + ((size_t)ic * IH + gy) * IW;
        float* dstrow = s_in + (ic * IN_ROWS + r) * IN_WS;
        #pragma unroll
        for (int cc = 0; cc < 3; cc++) {
            int c = lane + cc * 32;
            if (c < 68) {
                int gx = bx0 + c;
                float v = 0.0f;
                if (gy < IH && gx < IW) v = __ldg(src + gx);
                if (c < 36)  dstrow[2 * c] = v;
                if (c >= 32) dstrow[2 * (c - 32) + 1] = v;
            }
        }
    }

    // ---- Load packed active weights, duplicated as (w,w) pairs ----
    #pragma unroll 1
    for (int idx = tid; idx < NIC * 25 * NACT; idx += NTHREADS) {
        int ic   = idx / (25 * NACT);
        int rem  = idx % (25 * NACT);
        int k    = rem / NACT;
        int slot = rem % NACT;
        int oc   = active(ic, slot);
        float wv = W[oc * (NIC * 25) + ic * 25 + k];
        s_w[(ic * 25 + k) * (2 * NACT) + 2 * slot]     = wv;
        s_w[(ic * 25 + k) * (2 * NACT) + 2 * slot + 1] = wv;
    }
    if (tid < NOC) s_b[tid] = b[tid];
    __syncthreads();

    // ---- Compute ----
    const int tx   = lane;           // owns output cols bx0+tx and bx0+tx+32
    const int row0 = warp * RPT;     // owns output rows by0+row0 .. +RPT-1

    ull acc[RPT][NOC];
    #pragma unroll
    for (int r = 0; r < RPT; r++)
        #pragma unroll
        for (int o = 0; o < NOC; o++) acc[r][o] = 0ull;

    conv_ic<0>(s_in, s_w, acc, row0, tx);
    conv_ic<1>(s_in, s_w, acc, row0, tx);
    conv_ic<2>(s_in, s_w, acc, row0, tx);
    conv_ic<3>(s_in, s_w, acc, row0, tx);
    conv_ic<4>(s_in, s_w, acc, row0, tx);
    conv_ic<5>(s_in, s_w, acc, row0, tx);

    // ---- Epilogue: add bias, store ----
    const int x0 = bx0 + tx;
    const int x1 = x0 + 32;
    #pragma unroll
    for (int r = 0; r < RPT; r++) {
        int y = by0 + row0 + r;
        if (y >= OH) continue;
        #pragma unroll
        for (int oc = 0; oc < NOC; oc++) {
            float bo = s_b[oc];
            float lo = __uint_as_float((unsigned)(acc[r][oc] & 0xffffffffull)) + bo;
            float hi = __uint_as_float((unsigned)(acc[r][oc] >> 32)) + bo;
            size_t base = ((size_t)(n * NOC + oc) * OH + y) * OW;
            if (x0 < OW) out[base + x0] = lo;
            if (x1 < OW) out[base + x1] = hi;
        }
    }
}

extern "C" void kernel_launch(void* const* d_in, const int* in_sizes, int n_in,
                              void* d_out, int out_size) {
    const float* x = (const float*)d_in[0];
    const float* W = (const float*)d_in[1];
    const float* b = (const float*)d_in[2];
    float* out = (float*)d_out;

    const int smem_bytes = (NIC * IN_ROWS * IN_WS + NIC * 25 * 2 * NACT + NOC) * 4;
    cudaFuncSetAttribute(conv_c3_kernel,
                         cudaFuncAttributeMaxDynamicSharedMemorySize, smem_bytes);

    const int n_batch = in_sizes[0] / (NIC * IH * IW);   // 64
    dim3 grid((OW + TILE_W - 1) / TILE_W,    // 8
              (OH + TILE_H - 1) / TILE_H,    // 32
              n_batch);                       // 64
    conv_c3_kernel<<<grid, NTHREADS, smem_bytes>>>(x, W, b, out);
}